// round 1
// baseline (speedup 1.0000x reference)
#include <cuda_runtime.h>

#define NGRAPH 8192
#define NP 32
#define HDIM 128
#define NEDGE 524288

typedef unsigned long long u64;

// Per-graph 32x32 edge-count matrices: adj[g][dst_local][src_local]
__device__ int g_adj[NGRAPH * 1024];  // 33.5 MB static scratch (allowed)

__global__ void k_zero_adj() {
  int i = blockIdx.x * blockDim.x + threadIdx.x;
  int stride = gridDim.x * blockDim.x;
  int4* p = (int4*)g_adj;
  const int n4 = NGRAPH * 1024 / 4;
  int4 z = make_int4(0, 0, 0, 0);
  for (; i < n4; i += stride) p[i] = z;
}

__global__ void k_build_adj(const int* __restrict__ src, const int* __restrict__ dst) {
  int e = blockIdx.x * blockDim.x + threadIdx.x;
  if (e >= NEDGE) return;
  int d = dst[e];
  int s = src[e];
  // src and dst are in the same graph by construction
  atomicAdd(&g_adj[((d >> 5) << 10) + ((d & 31) << 5) + (s & 31)], 1);
}

// ---- packed fp32x2 helpers (Blackwell FFMA2, PTX-only) ----
__device__ __forceinline__ u64 ffma2(u64 a, u64 b, u64 c) {
  u64 d;
  asm("fma.rn.f32x2 %0, %1, %2, %3;" : "=l"(d) : "l"(a), "l"(b), "l"(c));
  return d;
}
__device__ __forceinline__ float f2red(u64 v) {
  return __uint_as_float((unsigned)v) + __uint_as_float((unsigned)(v >> 32));
}
__device__ __forceinline__ float sigf(float x) {
  return 1.f / (1.f + __expf(-x));
}
__device__ __forceinline__ float tanh_fast(float x) {
  float e2x = __expf(2.f * x);           // inf-safe: 1 - 2/(inf+1) = 1
  return 1.f - 2.f / (e2x + 1.f);
}

// ---- shared memory layout (floats), total 33888 floats = 135552 B ----
#define OFF_F    0       // feat        [32][128]
#define OFF_A    4096    // counts      [32][33] padded
#define OFF_RIN  5152    // 1/max(deg_in,1)  [32]
#define OFF_ROUT 5184    // 1/max(deg_out,1) [32]
#define OFF_FIN  5216    // feat_in     [32][128]
#define OFF_FOUT 9312    // feat_out    [32][128]
#define OFF_AA   13408   // a           [32][256]
#define OFF_GI   21600   // gi          [32][384]
#define OFF_HN   5216    // hn          [32][128]  (reuses FIN)
#define OFF_EV   9312    // sig*w_e     [32][128]  (reuses FOUT)
#define OFF_V    4096    // feat_v      [128]      (reuses A)
#define OFF_AL   4224    // alpha       [32]       (reuses A)
#define SMEM_FLOATS 33888
#define SMEM_BYTES  (SMEM_FLOATS * 4)

__global__ void __launch_bounds__(256, 1) k_fused(
    const float* __restrict__ feat, const float* __restrict__ cnt,
    const float* __restrict__ W_in, const float* __restrict__ b_in,
    const float* __restrict__ W_og, const float* __restrict__ b_og,
    const float* __restrict__ W_ih, const float* __restrict__ b_ih,
    const float* __restrict__ W_hh, const float* __restrict__ b_hh,
    const float* __restrict__ W_u,  const float* __restrict__ W_v,
    const float* __restrict__ b_v,  const float* __restrict__ w_e,
    float* __restrict__ out) {
  extern __shared__ float sm[];
  const int g = blockIdx.x;
  const int t = threadIdx.x;

  float* sF   = sm + OFF_F;
  float* sA   = sm + OFF_A;
  float* rin  = sm + OFF_RIN;
  float* rout = sm + OFF_ROUT;
  float* sFIN = sm + OFF_FIN;
  float* sFOUT= sm + OFF_FOUT;
  float* sAA  = sm + OFF_AA;
  float* sGI  = sm + OFF_GI;
  float* sHN  = sm + OFF_HN;
  float* sEV  = sm + OFF_EV;
  float* sV   = sm + OFF_V;
  float* sAl  = sm + OFF_AL;

  // ---- load feat tile (16 KB) and adjacency counts ----
  {
    const float4* fg = (const float4*)(feat + (size_t)g * NP * HDIM);
    float4* f4 = (float4*)sF;
#pragma unroll
    for (int i = 0; i < 4; i++) f4[t + 256 * i] = fg[t + 256 * i];
    const int* adjg = &g_adj[g << 10];
#pragma unroll
    for (int i = t; i < 1024; i += 256)
      sA[(i >> 5) * 33 + (i & 31)] = (float)adjg[i];
  }
  __syncthreads();

  // ---- degrees ----
  if (t < 32) {
    float s = 0.f;
#pragma unroll
    for (int k = 0; k < 32; k++) s += sA[t * 33 + k];
    rin[t] = 1.f / fmaxf(s, 1.f);
  } else if (t < 64) {
    int n = t - 32;
    float s = 0.f;
#pragma unroll
    for (int k = 0; k < 32; k++) s += sA[k * 33 + n];
    rout[n] = 1.f / fmaxf(s, 1.f);
  }

  // ---- P1: feat_in = F@W_in^T + b_in ; feat_out = F@W_og^T + b_og ----
  {
    const int rg = t >> 6;        // 4 row-groups of 8 rows
    const int cg = t & 63;        // 64 col-groups of 2 cols
    const int r0 = rg * 8;
    const int c0 = cg * 2;
    u64 accA[8][2], accB[8][2];
#pragma unroll
    for (int r = 0; r < 8; r++)
#pragma unroll
      for (int c = 0; c < 2; c++) { accA[r][c] = 0ull; accB[r][c] = 0ull; }
    const ulonglong2* Wi = (const ulonglong2*)W_in;  // 32 ull2 per row
    const ulonglong2* Wo = (const ulonglong2*)W_og;
    const ulonglong2* F2 = (const ulonglong2*)sF;
#pragma unroll 2
    for (int k4 = 0; k4 < 32; k4++) {
      ulonglong2 wa0 = Wi[(c0    ) * 32 + k4];
      ulonglong2 wa1 = Wi[(c0 + 1) * 32 + k4];
      ulonglong2 wb0 = Wo[(c0    ) * 32 + k4];
      ulonglong2 wb1 = Wo[(c0 + 1) * 32 + k4];
#pragma unroll
      for (int r = 0; r < 8; r++) {
        ulonglong2 f = F2[(r0 + r) * 32 + k4];
        accA[r][0] = ffma2(f.x, wa0.x, accA[r][0]);
        accA[r][0] = ffma2(f.y, wa0.y, accA[r][0]);
        accA[r][1] = ffma2(f.x, wa1.x, accA[r][1]);
        accA[r][1] = ffma2(f.y, wa1.y, accA[r][1]);
        accB[r][0] = ffma2(f.x, wb0.x, accB[r][0]);
        accB[r][0] = ffma2(f.y, wb0.y, accB[r][0]);
        accB[r][1] = ffma2(f.x, wb1.x, accB[r][1]);
        accB[r][1] = ffma2(f.y, wb1.y, accB[r][1]);
      }
    }
#pragma unroll
    for (int r = 0; r < 8; r++)
#pragma unroll
      for (int c = 0; c < 2; c++) {
        sFIN [(r0 + r) * HDIM + c0 + c] = f2red(accA[r][c]) + b_in[c0 + c];
        sFOUT[(r0 + r) * HDIM + c0 + c] = f2red(accB[r][c]) + b_og[c0 + c];
      }
  }
  __syncthreads();

  // ---- P2: a = [ (A@feat_in)/deg_in | (A^T@feat_out)/deg_out ]  (K=32) ----
  {
    float acc[32];
#pragma unroll
    for (int n = 0; n < 32; n++) acc[n] = 0.f;
    if (t < 128) {
      const int j = t;
#pragma unroll
      for (int k = 0; k < 32; k++) {
        float f = sFIN[k * HDIM + j];
#pragma unroll
        for (int n = 0; n < 32; n++) acc[n] += sA[n * 33 + k] * f;
      }
#pragma unroll
      for (int n = 0; n < 32; n++) sAA[n * 256 + j] = acc[n] * rin[n];
    } else {
      const int j = t - 128;
#pragma unroll
      for (int k = 0; k < 32; k++) {
        float f = sFOUT[k * HDIM + j];
#pragma unroll
        for (int n = 0; n < 32; n++) acc[n] += sA[k * 33 + n] * f;
      }
#pragma unroll
      for (int n = 0; n < 32; n++) sAA[n * 256 + 128 + j] = acc[n] * rout[n];
    }
  }
  __syncthreads();

  // ---- P3: gi = a @ W_ih^T + b_ih   [32][384], K=256 ----
  {
    const int j  = t & 127;            // base col; gates at j, j+128, j+256
    const int r0 = (t >> 7) * 16;      // 2 row-groups of 16 rows
    u64 a0[16], a1[16], a2[16];
#pragma unroll
    for (int r = 0; r < 16; r++) { a0[r] = 0ull; a1[r] = 0ull; a2[r] = 0ull; }
    const ulonglong2* W2 = (const ulonglong2*)W_ih;  // 64 ull2 per row (256 f)
    const ulonglong2* A2 = (const ulonglong2*)sAA;   // 64 ull2 per row
#pragma unroll 2
    for (int k4 = 0; k4 < 64; k4++) {
      ulonglong2 w0 = W2[(j      ) * 64 + k4];
      ulonglong2 w1 = W2[(j + 128) * 64 + k4];
      ulonglong2 w2 = W2[(j + 256) * 64 + k4];
#pragma unroll
      for (int r = 0; r < 16; r++) {
        ulonglong2 f = A2[(r0 + r) * 64 + k4];
        a0[r] = ffma2(f.x, w0.x, a0[r]); a0[r] = ffma2(f.y, w0.y, a0[r]);
        a1[r] = ffma2(f.x, w1.x, a1[r]); a1[r] = ffma2(f.y, w1.y, a1[r]);
        a2[r] = ffma2(f.x, w2.x, a2[r]); a2[r] = ffma2(f.y, w2.y, a2[r]);
      }
    }
    float bj0 = b_ih[j], bj1 = b_ih[j + 128], bj2 = b_ih[j + 256];
#pragma unroll
    for (int r = 0; r < 16; r++) {
      int n = r0 + r;
      sGI[n * 384 + j      ] = f2red(a0[r]) + bj0;
      sGI[n * 384 + j + 128] = f2red(a1[r]) + bj1;
      sGI[n * 384 + j + 256] = f2red(a2[r]) + bj2;
    }
  }
  __syncthreads();

  // ---- P4: gh = F @ W_hh^T + b_hh (fused), then GRU gates -> hn ----
  {
    const int j  = t & 127;
    const int r0 = (t >> 7) * 16;
    u64 h0[16], h1[16], h2[16];
#pragma unroll
    for (int r = 0; r < 16; r++) { h0[r] = 0ull; h1[r] = 0ull; h2[r] = 0ull; }
    const ulonglong2* W2 = (const ulonglong2*)W_hh;  // 32 ull2 per row (128 f)
    const ulonglong2* F2 = (const ulonglong2*)sF;
#pragma unroll 2
    for (int k4 = 0; k4 < 32; k4++) {
      ulonglong2 w0 = W2[(j      ) * 32 + k4];
      ulonglong2 w1 = W2[(j + 128) * 32 + k4];
      ulonglong2 w2 = W2[(j + 256) * 32 + k4];
#pragma unroll
      for (int r = 0; r < 16; r++) {
        ulonglong2 f = F2[(r0 + r) * 32 + k4];
        h0[r] = ffma2(f.x, w0.x, h0[r]); h0[r] = ffma2(f.y, w0.y, h0[r]);
        h1[r] = ffma2(f.x, w1.x, h1[r]); h1[r] = ffma2(f.y, w1.y, h1[r]);
        h2[r] = ffma2(f.x, w2.x, h2[r]); h2[r] = ffma2(f.y, w2.y, h2[r]);
      }
    }
    float bh0 = b_hh[j], bh1 = b_hh[j + 128], bh2 = b_hh[j + 256];
#pragma unroll
    for (int r = 0; r < 16; r++) {
      int n = r0 + r;
      float gr = sGI[n * 384 + j      ] + f2red(h0[r]) + bh0;
      float gz = sGI[n * 384 + j + 128] + f2red(h1[r]) + bh1;
      float i_n = sGI[n * 384 + j + 256];
      float h_n = f2red(h2[r]) + bh2;
      float rr = sigf(gr);
      float zz = sigf(gz);
      float ng = tanh_fast(i_n + rr * h_n);
      float h  = sF[n * HDIM + j];
      sHN[n * HDIM + j] = (1.f - zz) * ng + zz * h;
    }
  }
  __syncthreads();

  // ---- P5a: feat_v = hn[31] @ W_v^T + b_v  [128] ----
  if (t < 128) {
    u64 acc = 0ull;
    const ulonglong2* W2 = (const ulonglong2*)W_v;
    const ulonglong2* H2 = (const ulonglong2*)(sHN + 31 * HDIM);
#pragma unroll
    for (int k4 = 0; k4 < 32; k4++) {
      ulonglong2 w = W2[t * 32 + k4];
      ulonglong2 f = H2[k4];
      acc = ffma2(f.x, w.x, acc);
      acc = ffma2(f.y, w.y, acc);
    }
    sV[t] = f2red(acc) + b_v[t];
  }
  __syncthreads();

  // ---- P5b: ev[n][j] = sigmoid(hn@W_u^T + v[j]) * w_e[j] ----
  {
    const int j  = t & 127;
    const int r0 = (t >> 7) * 16;
    u64 u[16];
#pragma unroll
    for (int r = 0; r < 16; r++) u[r] = 0ull;
    const ulonglong2* W2 = (const ulonglong2*)W_u;
    const ulonglong2* H2 = (const ulonglong2*)sHN;
#pragma unroll 2
    for (int k4 = 0; k4 < 32; k4++) {
      ulonglong2 w = W2[j * 32 + k4];
#pragma unroll
      for (int r = 0; r < 16; r++) {
        ulonglong2 f = H2[(r0 + r) * 32 + k4];
        u[r] = ffma2(f.x, w.x, u[r]);
        u[r] = ffma2(f.y, w.y, u[r]);
      }
    }
    float vj = sV[j], wej = w_e[j];
#pragma unroll
    for (int r = 0; r < 16; r++) {
      float uu = f2red(u[r]) + vj;
      sEV[(r0 + r) * HDIM + j] = wej * sigf(uu);
    }
  }
  __syncthreads();

  // ---- P5c: e[n] = sum_j ev[n][j];  alpha[n] = e[n]*cnt[n] ----
  {
    const int warp = t >> 5, lane = t & 31;
#pragma unroll
    for (int rr = 0; rr < 4; rr++) {
      int n = warp * 4 + rr;
      float s = sEV[n * HDIM + lane]      + sEV[n * HDIM + lane + 32]
              + sEV[n * HDIM + lane + 64] + sEV[n * HDIM + lane + 96];
#pragma unroll
      for (int o = 16; o; o >>= 1) s += __shfl_xor_sync(0xffffffffu, s, o);
      if (lane == 0) sAl[n] = s * cnt[(size_t)g * NP + n];
    }
  }
  __syncthreads();

  // ---- P5d: output [ct_g | ct_l] ----
  if (t < 128) {
    float acc = 0.f;
#pragma unroll
    for (int n = 0; n < NP; n++) acc += sHN[n * HDIM + t] * sAl[n];
    out[(size_t)g * 2 * HDIM + t] = acc;
    out[(size_t)g * 2 * HDIM + HDIM + t] = sHN[31 * HDIM + t];
  }
}

extern "C" void kernel_launch(void* const* d_in, const int* in_sizes, int n_in,
                              void* d_out, int out_size) {
  const float* feat = (const float*)d_in[0];
  const float* cnt  = (const float*)d_in[1];
  const float* W_in = (const float*)d_in[2];
  const float* b_in = (const float*)d_in[3];
  const float* W_og = (const float*)d_in[4];
  const float* b_og = (const float*)d_in[5];
  const float* W_ih = (const float*)d_in[6];
  const float* b_ih = (const float*)d_in[7];
  const float* W_hh = (const float*)d_in[8];
  const float* b_hh = (const float*)d_in[9];
  const float* W_u  = (const float*)d_in[10];
  const float* W_v  = (const float*)d_in[11];
  const float* b_v  = (const float*)d_in[12];
  const float* w_e  = (const float*)d_in[13];
  const int*   src  = (const int*)d_in[14];
  const int*   dst  = (const int*)d_in[15];
  float* out = (float*)d_out;

  cudaFuncSetAttribute(k_fused, cudaFuncAttributeMaxDynamicSharedMemorySize,
                       SMEM_BYTES);

  k_zero_adj<<<512, 256>>>();
  k_build_adj<<<NEDGE / 256, 256>>>(src, dst);
  k_fused<<<NGRAPH, 256, SMEM_BYTES>>>(feat, cnt, W_in, b_in, W_og, b_og,
                                       W_ih, b_ih, W_hh, b_hh, W_u, W_v, b_v,
                                       w_e, out);
}

// round 2
// speedup vs baseline: 1.7693x; 1.7693x over previous
#include <cuda_runtime.h>

#define NGRAPH 8192
#define NP 32
#define HDIM 128
#define NEDGE 524288
#define NNODE (NGRAPH * NP)

typedef unsigned long long u64;

// ---- static device scratch (allocation-free rule) ----
__device__ int   g_adj[NGRAPH * 1024];              // 33.5 MB
__device__ float bufY  [(size_t)NNODE * 256];       // feat_in | feat_out
__device__ float bufAgg[(size_t)NNODE * 256];       // a_in | a_out
__device__ float bufG  [(size_t)NNODE * 512];       // r-sum | z-sum | i_n | h_n
__device__ float bufHN [(size_t)NNODE * 128];       // hn
__device__ float bufU  [(size_t)NNODE * 128];       // hn @ W_u^T
__device__ float bufFV [(size_t)NGRAPH * 128];      // feat_v

// ---- helpers ----
__device__ __forceinline__ u64 ffma2(u64 a, u64 b, u64 c) {
  u64 d;
  asm("fma.rn.f32x2 %0, %1, %2, %3;" : "=l"(d) : "l"(a), "l"(b), "l"(c));
  return d;
}
__device__ __forceinline__ u64 fpack(float x, float y) {
  u64 r;
  asm("mov.b64 %0, {%1, %2};" : "=l"(r) : "f"(x), "f"(y));
  return r;
}
__device__ __forceinline__ float lof(u64 v) { return __uint_as_float((unsigned)v); }
__device__ __forceinline__ float hif(u64 v) { return __uint_as_float((unsigned)(v >> 32)); }
__device__ __forceinline__ float sigf(float x) { return 1.f / (1.f + __expf(-x)); }
__device__ __forceinline__ float tanh_fast(float x) {
  float e2x = __expf(2.f * x);
  return 1.f - 2.f / (e2x + 1.f);
}

// ---- adjacency ----
__global__ void k_zero_adj() {
  int i = blockIdx.x * blockDim.x + threadIdx.x;
  int stride = gridDim.x * blockDim.x;
  int4* p = (int4*)g_adj;
  const int n4 = NGRAPH * 1024 / 4;
  int4 z = make_int4(0, 0, 0, 0);
  for (; i < n4; i += stride) p[i] = z;
}

__global__ void k_build_adj(const int* __restrict__ src, const int* __restrict__ dst) {
  int e = blockIdx.x * blockDim.x + threadIdx.x;
  if (e >= NEDGE) return;
  int d = dst[e];
  int s = src[e];
  atomicAdd(&g_adj[((d >> 5) << 10) + ((d & 31) << 5) + (s & 31)], 1);
}

// ---- generic tiled SGEMM: C[m][coff+n] = sum_k A'[m][k] * B'[n][k] + bias ----
// A' is [A1 | A2] split at Ksplit (col-concatenated), likewise B' = [B1 | B2].
// BM=BN=128, BK=16, 256 threads, 8x8 microtile in fp32x2.
__device__ __forceinline__ void ldg_tile(
    const float* __restrict__ S1, int ld1,
    const float* __restrict__ S2, int ld2, int Ksplit,
    int m0, int k0, int tid, float4* v) {
  const float* src;
  int ld;
  if (k0 < Ksplit) { src = S1; ld = ld1; }
  else { src = S2; ld = ld2; k0 -= Ksplit; }
#pragma unroll
  for (int l = 0; l < 2; l++) {
    int e = tid + l * 256;
    int row = e >> 2, kq = e & 3;
    v[l] = *(const float4*)(src + (size_t)(m0 + row) * ld + k0 + kq * 4);
  }
}
__device__ __forceinline__ void sts_tile(float (*S)[132], int tid, const float4* v) {
#pragma unroll
  for (int l = 0; l < 2; l++) {
    int e = tid + l * 256;
    int row = e >> 2, kq = e & 3;
    S[kq * 4 + 0][row] = v[l].x;
    S[kq * 4 + 1][row] = v[l].y;
    S[kq * 4 + 2][row] = v[l].z;
    S[kq * 4 + 3][row] = v[l].w;
  }
}

__global__ void __launch_bounds__(256, 2) k_gemm(
    const float* __restrict__ A1, int lda1,
    const float* __restrict__ A2, int lda2,
    const float* __restrict__ B1, int ldb1,
    const float* __restrict__ B2, int ldb2,
    int Ksplit, int Ktot,
    const float* __restrict__ bias1, const float* __restrict__ bias2,
    float* __restrict__ C, int ldc, int coff) {
  __shared__ float As[2][16][132];
  __shared__ float Bs[2][16][132];
  const int tid = threadIdx.x;
  const int m0 = blockIdx.x * 128;
  const int tr = tid >> 4, tc = tid & 15;

  float4 va[2], vb[2];
  ldg_tile(A1, lda1, A2, lda2, Ksplit, m0, 0, tid, va);
  ldg_tile(B1, ldb1, B2, ldb2, Ksplit, 0, 0, tid, vb);
  sts_tile(As[0], tid, va);
  sts_tile(Bs[0], tid, vb);
  __syncthreads();

  u64 acc[4][8];
#pragma unroll
  for (int rp = 0; rp < 4; rp++)
#pragma unroll
    for (int c = 0; c < 8; c++) acc[rp][c] = 0ull;

  const int nkb = Ktot >> 4;
  for (int kb = 0; kb < nkb; kb++) {
    const int cur = kb & 1;
    if (kb + 1 < nkb) {
      ldg_tile(A1, lda1, A2, lda2, Ksplit, m0, (kb + 1) * 16, tid, va);
      ldg_tile(B1, ldb1, B2, ldb2, Ksplit, 0, (kb + 1) * 16, tid, vb);
    }
#pragma unroll 4
    for (int k = 0; k < 16; k++) {
      ulonglong2 a01 = *(const ulonglong2*)&As[cur][k][tr * 8];
      ulonglong2 a23 = *(const ulonglong2*)&As[cur][k][tr * 8 + 4];
      float4 b0 = *(const float4*)&Bs[cur][k][tc * 8];
      float4 b1 = *(const float4*)&Bs[cur][k][tc * 8 + 4];
      u64 ap[4];
      ap[0] = a01.x; ap[1] = a01.y; ap[2] = a23.x; ap[3] = a23.y;
      float bb[8];
      bb[0] = b0.x; bb[1] = b0.y; bb[2] = b0.z; bb[3] = b0.w;
      bb[4] = b1.x; bb[5] = b1.y; bb[6] = b1.z; bb[7] = b1.w;
#pragma unroll
      for (int c = 0; c < 8; c++) {
        u64 bp = fpack(bb[c], bb[c]);
#pragma unroll
        for (int rp = 0; rp < 4; rp++)
          acc[rp][c] = ffma2(ap[rp], bp, acc[rp][c]);
      }
    }
    if (kb + 1 < nkb) {
      const int nxt = cur ^ 1;
      sts_tile(As[nxt], tid, va);
      sts_tile(Bs[nxt], tid, vb);
    }
    __syncthreads();
  }

  // epilogue: bias + store
  float bv[8];
#pragma unroll
  for (int c = 0; c < 8; c++) {
    float b = bias1 ? bias1[tc * 8 + c] : 0.f;
    if (bias2) b += bias2[tc * 8 + c];
    bv[c] = b;
  }
#pragma unroll
  for (int rp = 0; rp < 4; rp++) {
    float lo[8], hi[8];
#pragma unroll
    for (int c = 0; c < 8; c++) {
      lo[c] = lof(acc[rp][c]) + bv[c];
      hi[c] = hif(acc[rp][c]) + bv[c];
    }
    int row = m0 + tr * 8 + rp * 2;
    float* p0 = C + (size_t)row * ldc + coff + tc * 8;
    float* p1 = p0 + ldc;
    ((float4*)p0)[0] = make_float4(lo[0], lo[1], lo[2], lo[3]);
    ((float4*)p0)[1] = make_float4(lo[4], lo[5], lo[6], lo[7]);
    ((float4*)p1)[0] = make_float4(hi[0], hi[1], hi[2], hi[3]);
    ((float4*)p1)[1] = make_float4(hi[4], hi[5], hi[6], hi[7]);
  }
}

// ---- per-graph edge aggregation: Agg = [ (A@fin)/deg_in | (A^T@fout)/deg_out ] ----
__global__ void __launch_bounds__(256) k_agg(const float* __restrict__ Y,
                                             float* __restrict__ Agg) {
  __shared__ float sY[32 * 256];
  __shared__ float sA[32 * 33];
  __shared__ float rin[32], rout[32];
  const int g = blockIdx.x, t = threadIdx.x;

  const float4* src = (const float4*)(Y + (size_t)g * 32 * 256);
  float4* d4 = (float4*)sY;
#pragma unroll
  for (int i = 0; i < 8; i++) d4[t + 256 * i] = src[t + 256 * i];
  const int* adjg = &g_adj[g << 10];
#pragma unroll
  for (int i = t; i < 1024; i += 256)
    sA[(i >> 5) * 33 + (i & 31)] = (float)adjg[i];
  __syncthreads();

  if (t < 32) {
    float s = 0.f;
#pragma unroll
    for (int k = 0; k < 32; k++) s += sA[t * 33 + k];
    rin[t] = 1.f / fmaxf(s, 1.f);
  } else if (t < 64) {
    int n = t - 32;
    float s = 0.f;
#pragma unroll
    for (int k = 0; k < 32; k++) s += sA[k * 33 + n];
    rout[n] = 1.f / fmaxf(s, 1.f);
  }
  __syncthreads();

  float acc[32];
#pragma unroll
  for (int n = 0; n < 32; n++) acc[n] = 0.f;
  if (t < 128) {
    const int j = t;
#pragma unroll
    for (int k = 0; k < 32; k++) {
      float f = sY[k * 256 + j];
#pragma unroll
      for (int n = 0; n < 32; n++) acc[n] += sA[n * 33 + k] * f;
    }
#pragma unroll
    for (int n = 0; n < 32; n++)
      Agg[((size_t)g * 32 + n) * 256 + j] = acc[n] * rin[n];
  } else {
    const int j = t - 128;
#pragma unroll
    for (int k = 0; k < 32; k++) {
      float f = sY[k * 256 + 128 + j];
#pragma unroll
      for (int n = 0; n < 32; n++) acc[n] += sA[k * 33 + n] * f;
    }
#pragma unroll
    for (int n = 0; n < 32; n++)
      Agg[((size_t)g * 32 + n) * 256 + 128 + j] = acc[n] * rout[n];
  }
}

// ---- GRU elementwise: hn from G=[r-sum|z-sum|i_n|h_n] and feat ----
__global__ void k_gru(const float* __restrict__ G, const float* __restrict__ feat,
                      float* __restrict__ HN) {
  size_t i = (size_t)blockIdx.x * 256 + threadIdx.x;  // over N*32 float4s
  const float4* G4 = (const float4*)G;
  const float4* F4 = (const float4*)feat;
  float4* H4 = (float4*)HN;
  size_t n = i >> 5;
  int jq = (int)(i & 31);
  float4 gr = G4[n * 128 + jq];
  float4 gz = G4[n * 128 + 32 + jq];
  float4 gn = G4[n * 128 + 64 + jq];
  float4 gh = G4[n * 128 + 96 + jq];
  float4 f = F4[n * 32 + jq];
  float4 o;
  {
    float r = sigf(gr.x), z = sigf(gz.x);
    float ng = tanh_fast(gn.x + r * gh.x);
    o.x = (1.f - z) * ng + z * f.x;
  }
  {
    float r = sigf(gr.y), z = sigf(gz.y);
    float ng = tanh_fast(gn.y + r * gh.y);
    o.y = (1.f - z) * ng + z * f.y;
  }
  {
    float r = sigf(gr.z), z = sigf(gz.z);
    float ng = tanh_fast(gn.z + r * gh.z);
    o.z = (1.f - z) * ng + z * f.z;
  }
  {
    float r = sigf(gr.w), z = sigf(gz.w);
    float ng = tanh_fast(gn.w + r * gh.w);
    o.w = (1.f - z) * ng + z * f.w;
  }
  H4[n * 32 + jq] = o;
}

// ---- per-graph attention readout ----
__global__ void __launch_bounds__(256) k_readout(
    const float* __restrict__ HN, const float* __restrict__ U,
    const float* __restrict__ FV, const float* __restrict__ cnt,
    const float* __restrict__ w_e, float* __restrict__ out) {
  __shared__ float sH[32 * 128];
  __shared__ float sU[32 * 128];
  __shared__ float sv[128];
  __shared__ float al[32];
  const int g = blockIdx.x, t = threadIdx.x;

  const float4* h4 = (const float4*)(HN + (size_t)g * 32 * 128);
  const float4* u4 = (const float4*)(U + (size_t)g * 32 * 128);
  float4* a4 = (float4*)sH;
  float4* b4 = (float4*)sU;
#pragma unroll
  for (int i = 0; i < 4; i++) {
    a4[t + 256 * i] = h4[t + 256 * i];
    b4[t + 256 * i] = u4[t + 256 * i];
  }
  if (t < 128) sv[t] = FV[(size_t)g * 128 + t];
  __syncthreads();

  {
    const int j = t & 127, rh = (t >> 7) * 16;
    float vj = sv[j], wej = w_e[j];
#pragma unroll
    for (int r = 0; r < 16; r++) {
      int n = rh + r;
      sU[n * 128 + j] = wej * sigf(sU[n * 128 + j] + vj);
    }
  }
  __syncthreads();

  {
    const int w = t >> 5, lane = t & 31;
#pragma unroll
    for (int rr = 0; rr < 4; rr++) {
      int n = w * 4 + rr;
      float s = sU[n * 128 + lane] + sU[n * 128 + lane + 32] +
                sU[n * 128 + lane + 64] + sU[n * 128 + lane + 96];
#pragma unroll
      for (int o = 16; o; o >>= 1) s += __shfl_xor_sync(0xffffffffu, s, o);
      if (lane == 0) al[n] = s * cnt[(size_t)g * 32 + n];
    }
  }
  __syncthreads();

  if (t < 128) {
    float acc = 0.f;
#pragma unroll
    for (int n = 0; n < 32; n++) acc += sH[n * 128 + t] * al[n];
    out[(size_t)g * 256 + t] = acc;
    out[(size_t)g * 256 + 128 + t] = sH[31 * 128 + t];
  }
}

extern "C" void kernel_launch(void* const* d_in, const int* in_sizes, int n_in,
                              void* d_out, int out_size) {
  const float* feat = (const float*)d_in[0];
  const float* cnt  = (const float*)d_in[1];
  const float* W_in = (const float*)d_in[2];
  const float* b_in = (const float*)d_in[3];
  const float* W_og = (const float*)d_in[4];
  const float* b_og = (const float*)d_in[5];
  const float* W_ih = (const float*)d_in[6];
  const float* b_ih = (const float*)d_in[7];
  const float* W_hh = (const float*)d_in[8];
  const float* b_hh = (const float*)d_in[9];
  const float* W_u  = (const float*)d_in[10];
  const float* W_v  = (const float*)d_in[11];
  const float* b_v  = (const float*)d_in[12];
  const float* w_e  = (const float*)d_in[13];
  const int*   src  = (const int*)d_in[14];
  const int*   dst  = (const int*)d_in[15];
  float* out = (float*)d_out;

  float *Y, *Agg, *G, *HN, *U, *FV;
  cudaGetSymbolAddress((void**)&Y, bufY);
  cudaGetSymbolAddress((void**)&Agg, bufAgg);
  cudaGetSymbolAddress((void**)&G, bufG);
  cudaGetSymbolAddress((void**)&HN, bufHN);
  cudaGetSymbolAddress((void**)&U, bufU);
  cudaGetSymbolAddress((void**)&FV, bufFV);

  const int MB = NNODE / 128;  // 2048

  k_zero_adj<<<512, 256>>>();
  k_build_adj<<<NEDGE / 256, 256>>>(src, dst);

  // Y = feat @ [W_in|W_og]^T + b
  k_gemm<<<MB, 256>>>(feat, 128, feat, 128, W_in, 128, W_in, 128, 128, 128,
                      b_in, nullptr, Y, 256, 0);
  k_gemm<<<MB, 256>>>(feat, 128, feat, 128, W_og, 128, W_og, 128, 128, 128,
                      b_og, nullptr, Y, 256, 128);

  k_agg<<<NGRAPH, 256>>>(Y, Agg);

  // G slabs: r-sum, z-sum (K=384, dual source), i_n (K=256), h_n (K=128)
  k_gemm<<<MB, 256>>>(Agg, 256, feat, 128, W_ih, 256, W_hh, 128, 256, 384,
                      b_ih, b_hh, G, 512, 0);
  k_gemm<<<MB, 256>>>(Agg, 256, feat, 128, W_ih + 128 * 256, 256,
                      W_hh + 128 * 128, 128, 256, 384,
                      b_ih + 128, b_hh + 128, G, 512, 128);
  k_gemm<<<MB, 256>>>(Agg, 256, Agg, 256, W_ih + 256 * 256, 256,
                      W_ih + 256 * 256, 256, 256, 256,
                      b_ih + 256, nullptr, G, 512, 256);
  k_gemm<<<MB, 256>>>(feat, 128, feat, 128, W_hh + 256 * 128, 128,
                      W_hh + 256 * 128, 128, 128, 128,
                      b_hh + 256, nullptr, G, 512, 384);

  k_gru<<<NNODE * 32 / 256, 256>>>(G, feat, HN);

  // U = hn @ W_u^T
  k_gemm<<<MB, 256>>>(HN, 128, HN, 128, W_u, 128, W_u, 128, 128, 128,
                      nullptr, nullptr, U, 128, 0);
  // FV = hn[last] @ W_v^T + b_v  (strided A rows)
  k_gemm<<<NGRAPH / 128, 256>>>(HN + 31 * 128, 32 * 128, HN + 31 * 128, 32 * 128,
                                W_v, 128, W_v, 128, 128, 128,
                                b_v, nullptr, FV, 128, 0);

  k_readout<<<NGRAPH, 256>>>(HN, U, FV, cnt, w_e, out);
}

// round 4
// speedup vs baseline: 2.8358x; 1.6028x over previous
#include <cuda_runtime.h>
#include <cuda_bf16.h>
#include <cstdint>

#define NGRAPH 8192
#define NP 32
#define HDIM 128
#define NEDGE 524288
#define NNODE (NGRAPH * NP)

typedef __nv_bfloat16 bf16;

// ================= static device scratch =================
__device__ __align__(16) int  g_adj[NGRAPH * 1024];
__device__ __align__(16) bf16 g_featH[(size_t)NNODE * 128];
__device__ __align__(16) bf16 g_featL[(size_t)NNODE * 128];
__device__ __align__(16) bf16 g_AggH[(size_t)NNODE * 256];
__device__ __align__(16) bf16 g_AggL[(size_t)NNODE * 256];
__device__ __align__(16) float g_G[(size_t)NNODE * 512];
__device__ __align__(16) float g_HNf[(size_t)NNODE * 128];
__device__ __align__(16) bf16 g_HNh[(size_t)NNODE * 128];
__device__ __align__(16) bf16 g_HNl[(size_t)NNODE * 128];
__device__ __align__(16) float g_FV[(size_t)NGRAPH * 128];
__device__ __align__(16) float g_alpha[NNODE];
__device__ __align__(16) bf16 g_WioH[256 * 128], g_WioL[256 * 128];
__device__ __align__(16) bf16 g_WgH[512 * 384], g_WgL[512 * 384];
__device__ __align__(16) bf16 g_WuH[128 * 128], g_WuL[128 * 128];
__device__ __align__(16) bf16 g_WvH[128 * 128], g_WvL[128 * 128];
__device__ __align__(16) float g_biasY[256];
__device__ __align__(16) float g_biasG[512];

// ================= helpers =================
__device__ __forceinline__ uint32_t smem_to_u32(const void* p) {
  uint32_t a;
  asm("{ .reg .u64 tmp; cvta.to.shared.u64 tmp, %1; cvt.u32.u64 %0, tmp; }"
      : "=r"(a) : "l"(p));
  return a;
}
#define SWZ(off) ((off) ^ (((off) >> 3) & 0x70))

__device__ __forceinline__ void cp16(uint32_t dst, const void* src) {
  asm volatile("cp.async.cg.shared.global [%0], [%1], 16;" ::"r"(dst), "l"(src));
}
#define CP_COMMIT() asm volatile("cp.async.commit_group;" ::: "memory")
#define CP_WAIT(n) asm volatile("cp.async.wait_group %0;" ::"n"(n) : "memory")

__device__ __forceinline__ void ldsm_x4(uint32_t addr, uint32_t* r) {
  asm volatile("ldmatrix.sync.aligned.m8n8.x4.shared.b16 {%0,%1,%2,%3}, [%4];"
               : "=r"(r[0]), "=r"(r[1]), "=r"(r[2]), "=r"(r[3]) : "r"(addr));
}
__device__ __forceinline__ void mma16816(float* d, const uint32_t* a,
                                         const uint32_t* b) {
  asm volatile(
      "mma.sync.aligned.m16n8k16.row.col.f32.bf16.bf16.f32 "
      "{%0,%1,%2,%3}, {%4,%5,%6,%7}, {%8,%9}, {%0,%1,%2,%3};"
      : "+f"(d[0]), "+f"(d[1]), "+f"(d[2]), "+f"(d[3])
      : "r"(a[0]), "r"(a[1]), "r"(a[2]), "r"(a[3]), "r"(b[0]), "r"(b[1]));
}

__device__ __forceinline__ float sigf(float x) { return 1.f / (1.f + __expf(-x)); }
__device__ __forceinline__ float tanh_fast(float x) {
  float e2x = __expf(2.f * x);
  return 1.f - 2.f / (e2x + 1.f);
}
__device__ __forceinline__ void split2(float v, bf16* h, bf16* l) {
  bf16 hi = __float2bfloat16(v);
  *h = hi;
  *l = __float2bfloat16(v - __bfloat162float(hi));
}

// ================= adjacency =================
__global__ void k_zero_adj() {
  int i = blockIdx.x * blockDim.x + threadIdx.x;
  int stride = gridDim.x * blockDim.x;
  int4* p = (int4*)g_adj;
  const int n4 = NGRAPH * 1024 / 4;
  int4 z = make_int4(0, 0, 0, 0);
  for (; i < n4; i += stride) p[i] = z;
}
__global__ void k_build_adj(const int* __restrict__ src, const int* __restrict__ dst) {
  int e = blockIdx.x * blockDim.x + threadIdx.x;
  if (e >= NEDGE) return;
  int d = dst[e];
  int s = src[e];
  atomicAdd(&g_adj[((d >> 5) << 10) + ((d & 31) << 5) + (s & 31)], 1);
}

// ================= weight pack + split =================
__global__ void k_pack(const float* __restrict__ W_in, const float* __restrict__ W_og,
                       const float* __restrict__ W_ih, const float* __restrict__ W_hh,
                       const float* __restrict__ W_u, const float* __restrict__ W_v,
                       const float* __restrict__ b_in, const float* __restrict__ b_og,
                       const float* __restrict__ b_ih, const float* __restrict__ b_hh) {
  int i0 = blockIdx.x * 256 + threadIdx.x;
  int stride = gridDim.x * 256;
  for (int i = i0; i < 256 * 128; i += stride) {
    int r = i >> 7, c = i & 127;
    float v = (r < 128) ? W_in[r * 128 + c] : W_og[(r - 128) * 128 + c];
    split2(v, &g_WioH[i], &g_WioL[i]);
  }
  for (int i = i0; i < 512 * 384; i += stride) {
    int r = i / 384, c = i % 384;
    int blk = r >> 7, rr = r & 127;
    float v;
    if (blk == 0)      v = (c < 256) ? W_ih[rr * 256 + c] : W_hh[rr * 128 + (c - 256)];
    else if (blk == 1) v = (c < 256) ? W_ih[(128 + rr) * 256 + c] : W_hh[(128 + rr) * 128 + (c - 256)];
    else if (blk == 2) v = (c < 256) ? W_ih[(256 + rr) * 256 + c] : 0.f;
    else               v = (c < 256) ? 0.f : W_hh[(256 + rr) * 128 + (c - 256)];
    split2(v, &g_WgH[i], &g_WgL[i]);
  }
  for (int i = i0; i < 128 * 128; i += stride) {
    split2(W_u[i], &g_WuH[i], &g_WuL[i]);
    split2(W_v[i], &g_WvH[i], &g_WvL[i]);
  }
  for (int i = i0; i < 256; i += stride)
    g_biasY[i] = (i < 128) ? b_in[i] : b_og[i - 128];
  for (int i = i0; i < 512; i += stride) {
    float v;
    if (i < 256)      v = b_ih[i] + b_hh[i];
    else if (i < 384) v = b_ih[i];
    else              v = b_hh[i - 128];
    g_biasG[i] = v;
  }
}

__global__ void k_split_feat(const float* __restrict__ feat) {
  size_t i = (size_t)blockIdx.x * 256 + threadIdx.x;
  size_t stride = (size_t)gridDim.x * 256;
  const size_t n = (size_t)NNODE * 128;
  for (; i < n; i += stride) split2(feat[i], &g_featH[i], &g_featL[i]);
}

// ================= mma.sync GEMM, fused epilogues =================
// C = A'@B^T, A' = [A1|A2] split at Ksplit, bf16 hi/lo 3-pass.
// BM=128, BN=128 per CTA (grid.y = N/128 selects B rows), BK=64, 256 thr.
#define EPI_PLAIN 0
#define EPI_GATES 1
#define EPI_AGG 2
#define EPI_ALPHA 3

#define SG 65536          // bytes per stage
#define T_AH 0
#define T_AL 16384
#define T_BH 32768
#define T_BL 49152

template <int EPI>
__global__ void __launch_bounds__(256, 1) k_mma(
    const bf16* __restrict__ A1h, const bf16* __restrict__ A1l, int lda1,
    const bf16* __restrict__ A2h, const bf16* __restrict__ A2l, int lda2,
    int Ksplit,
    const bf16* __restrict__ Bh0, const bf16* __restrict__ Bl0, int ldb,
    const float* __restrict__ bias, float* __restrict__ C, int ldc,
    const float* __restrict__ cnt, const float* __restrict__ we) {
  extern __shared__ __align__(1024) char smem[];
  const uint32_t sb = smem_to_u32(smem);
  const int tid = threadIdx.x;
  const int lid = tid & 31, wid = tid >> 5;
  const int m0 = blockIdx.x * 128;
  const int nb = blockIdx.y;
  const int wm0 = (wid & 3) * 32, wn0 = (wid >> 2) * 64;

  const bf16* Bh = Bh0 + (size_t)nb * 128 * ldb;
  const bf16* Bl = Bl0 + (size_t)nb * 128 * ldb;

  int kstart = 0, kend = ldb;
  if (EPI == EPI_GATES) {
    if (nb == 2) kend = 256;
    else if (nb == 3) kstart = 256;
  }
  const int nchunks = (kend - kstart) >> 6;

  auto issue = [&](int kc, int s) {
    const bf16 *ah, *al;
    int ld, kk;
    if (kc < Ksplit) { ah = A1h; al = A1l; ld = lda1; kk = kc; }
    else { ah = A2h; al = A2l; ld = lda2; kk = kc - Ksplit; }
    uint32_t base = sb + s * SG;
#pragma unroll
    for (int i = 0; i < 4; i++) {
      int u = tid + 256 * i;
      int r = u >> 3, seg = u & 7;
      uint32_t d = SWZ(r * 128 + seg * 16);
      size_t aoff = (size_t)(m0 + r) * ld + kk + seg * 8;
      cp16(base + T_AH + d, ah + aoff);
      cp16(base + T_AL + d, al + aoff);
      size_t boff = (size_t)r * ldb + kc + seg * 8;
      cp16(base + T_BH + d, Bh + boff);
      cp16(base + T_BL + d, Bl + boff);
    }
    CP_COMMIT();
  };

  float acc[2][8][4];
#pragma unroll
  for (int mi = 0; mi < 2; mi++)
#pragma unroll
    for (int ni = 0; ni < 8; ni++)
#pragma unroll
      for (int q = 0; q < 4; q++) acc[mi][ni][q] = 0.f;

  issue(kstart, 0);
  for (int c = 0; c < nchunks; c++) {
    if (c + 1 < nchunks) {
      issue(kstart + (c + 1) * 64, (c + 1) & 1);
      CP_WAIT(1);
    } else {
      CP_WAIT(0);
    }
    __syncthreads();
    const uint32_t st = sb + (c & 1) * SG;
    const int j = lid >> 3, rr = lid & 7;
#pragma unroll
    for (int kk = 0; kk < 4; kk++) {
      uint32_t ah[2][4], al[2][4], bh[8][2], bl[8][2];
#pragma unroll
      for (int mi = 0; mi < 2; mi++) {
        int row = wm0 + mi * 16 + (j & 1) * 8 + rr;
        int kb = kk * 32 + (j >> 1) * 16;
        uint32_t ad = st + T_AH + SWZ(row * 128 + kb);
        ldsm_x4(ad, ah[mi]);
        ldsm_x4(ad + (T_AL - T_AH), al[mi]);
      }
#pragma unroll
      for (int p = 0; p < 4; p++) {
        int n = wn0 + p * 16 + (j >> 1) * 8 + rr;
        int kb = kk * 32 + (j & 1) * 16;
        uint32_t bd = st + T_BH + SWZ(n * 128 + kb);
        uint32_t t[4];
        ldsm_x4(bd, t);
        bh[2 * p][0] = t[0]; bh[2 * p][1] = t[1];
        bh[2 * p + 1][0] = t[2]; bh[2 * p + 1][1] = t[3];
        ldsm_x4(bd + (T_BL - T_BH), t);
        bl[2 * p][0] = t[0]; bl[2 * p][1] = t[1];
        bl[2 * p + 1][0] = t[2]; bl[2 * p + 1][1] = t[3];
      }
#pragma unroll
      for (int mi = 0; mi < 2; mi++)
#pragma unroll
        for (int ni = 0; ni < 8; ni++) {
          mma16816(acc[mi][ni], ah[mi], bh[ni]);
          mma16816(acc[mi][ni], ah[mi], bl[ni]);
          mma16816(acc[mi][ni], al[mi], bh[ni]);
        }
    }
    __syncthreads();
  }

  const int gp = lid >> 2, tg = lid & 3;

  if (EPI == EPI_PLAIN || EPI == EPI_GATES) {
    const int coff = (EPI == EPI_GATES) ? nb * 128 : 0;
#pragma unroll
    for (int mi = 0; mi < 2; mi++)
#pragma unroll
      for (int ni = 0; ni < 8; ni++) {
        int r0 = m0 + wm0 + mi * 16 + gp;
        int c = wn0 + ni * 8 + tg * 2;
        float b0 = 0.f, b1 = 0.f;
        if (EPI == EPI_PLAIN && bias) { b0 = bias[c]; b1 = bias[c + 1]; }
        float2 v0 = make_float2(acc[mi][ni][0] + b0, acc[mi][ni][1] + b1);
        float2 v1 = make_float2(acc[mi][ni][2] + b0, acc[mi][ni][3] + b1);
        *(float2*)&C[(size_t)r0 * ldc + coff + c] = v0;
        *(float2*)&C[(size_t)(r0 + 8) * ldc + coff + c] = v1;
      }
  } else if (EPI == EPI_AGG) {
    float* sC = (float*)smem;  // [128][132]
#pragma unroll
    for (int mi = 0; mi < 2; mi++)
#pragma unroll
      for (int ni = 0; ni < 8; ni++) {
        int r = wm0 + mi * 16 + gp;
        int c = wn0 + ni * 8 + tg * 2;
        float b0 = bias[nb * 128 + c], b1 = bias[nb * 128 + c + 1];
        sC[r * 132 + c] = acc[mi][ni][0] + b0;
        sC[r * 132 + c + 1] = acc[mi][ni][1] + b1;
        sC[(r + 8) * 132 + c] = acc[mi][ni][2] + b0;
        sC[(r + 8) * 132 + c + 1] = acc[mi][ni][3] + b1;
      }
    float* adjf = (float*)(smem + 67584);   // 4 x [32][33]
    float* rdeg = (float*)(smem + 67584 + 16896);
    const int g0 = m0 >> 5;
    for (int i = tid; i < 4096; i += 256) {
      int gl = i >> 10, rem = i & 1023;
      adjf[gl * 1056 + (rem >> 5) * 33 + (rem & 31)] =
          (float)g_adj[((g0 + gl) << 10) + rem];
    }
    __syncthreads();
    if (tid < 128) {
      int gl = tid >> 5, n = tid & 31;
      float s = 0.f;
#pragma unroll
      for (int k = 0; k < 32; k++)
        s += (nb == 0) ? adjf[gl * 1056 + n * 33 + k]
                       : adjf[gl * 1056 + k * 33 + n];
      rdeg[tid] = 1.f / fmaxf(s, 1.f);
    }
    __syncthreads();
    const int gl = tid >> 6, jj = tid & 63;
    float accA[32], accB[32];
#pragma unroll
    for (int n = 0; n < 32; n++) { accA[n] = 0.f; accB[n] = 0.f; }
    for (int k = 0; k < 32; k++) {
      float c0 = sC[(gl * 32 + k) * 132 + jj];
      float c1 = sC[(gl * 32 + k) * 132 + jj + 64];
#pragma unroll
      for (int n = 0; n < 32; n++) {
        float w = (nb == 0) ? adjf[gl * 1056 + n * 33 + k]
                            : adjf[gl * 1056 + k * 33 + n];
        accA[n] += w * c0;
        accB[n] += w * c1;
      }
    }
#pragma unroll
    for (int n = 0; n < 32; n++) {
      float rd = rdeg[gl * 32 + n];
      float v0 = accA[n] * rd, v1 = accB[n] * rd;
      size_t o = (size_t)(m0 + gl * 32 + n) * 256 + nb * 128;
      split2(v0, &g_AggH[o + jj], &g_AggL[o + jj]);
      split2(v1, &g_AggH[o + jj + 64], &g_AggL[o + jj + 64]);
    }
  } else if (EPI == EPI_ALPHA) {
    float* sC = (float*)smem;  // [128][132]
#pragma unroll
    for (int mi = 0; mi < 2; mi++)
#pragma unroll
      for (int ni = 0; ni < 8; ni++) {
        int r = wm0 + mi * 16 + gp;
        int c = wn0 + ni * 8 + tg * 2;
        sC[r * 132 + c] = acc[mi][ni][0];
        sC[r * 132 + c + 1] = acc[mi][ni][1];
        sC[(r + 8) * 132 + c] = acc[mi][ni][2];
        sC[(r + 8) * 132 + c + 1] = acc[mi][ni][3];
      }
    float* sFV = (float*)(smem + 67584);  // [4][128]
    const int g0 = m0 >> 5;
    for (int i = tid; i < 512; i += 256)
      sFV[i] = g_FV[(size_t)(g0 + (i >> 7)) * 128 + (i & 127)];
    __syncthreads();
    const int row = tid >> 1, half = tid & 1;
    float e = 0.f;
#pragma unroll 8
    for (int q = 0; q < 64; q++) {
      int jt = half * 64 + q;
      e += we[jt] * sigf(sC[row * 132 + jt] + sFV[(row >> 5) * 128 + jt]);
    }
    float o = __shfl_xor_sync(0xffffffffu, e, 1);
    if (half == 0) g_alpha[m0 + row] = (e + o) * cnt[m0 + row];
  }
}

// ================= GRU elementwise =================
__global__ void k_gru(const float* __restrict__ feat) {
  size_t i = (size_t)blockIdx.x * 256 + threadIdx.x;  // NNODE*32 float4 groups
  size_t n = i >> 5;
  int q = (int)(i & 31);
  const float4* G4 = (const float4*)g_G;
  const float4* B4 = (const float4*)g_biasG;
  const float4* F4 = (const float4*)feat;
  float4 gr = G4[n * 128 + q];
  float4 gz = G4[n * 128 + 32 + q];
  float4 gn = G4[n * 128 + 64 + q];
  float4 gh = G4[n * 128 + 96 + q];
  float4 br = B4[q], bz = B4[32 + q], bn = B4[64 + q], bhh = B4[96 + q];
  float4 f = F4[n * 32 + q];
  float hn[4];
  {
    float r = sigf(gr.x + br.x), z = sigf(gz.x + bz.x);
    hn[0] = (1.f - z) * tanh_fast(gn.x + bn.x + r * (gh.x + bhh.x)) + z * f.x;
  }
  {
    float r = sigf(gr.y + br.y), z = sigf(gz.y + bz.y);
    hn[1] = (1.f - z) * tanh_fast(gn.y + bn.y + r * (gh.y + bhh.y)) + z * f.y;
  }
  {
    float r = sigf(gr.z + br.z), z = sigf(gz.z + bz.z);
    hn[2] = (1.f - z) * tanh_fast(gn.z + bn.z + r * (gh.z + bhh.z)) + z * f.z;
  }
  {
    float r = sigf(gr.w + br.w), z = sigf(gz.w + bz.w);
    hn[3] = (1.f - z) * tanh_fast(gn.w + bn.w + r * (gh.w + bhh.w)) + z * f.w;
  }
  ((float4*)g_HNf)[n * 32 + q] = make_float4(hn[0], hn[1], hn[2], hn[3]);
  size_t e0 = n * 128 + q * 4;
#pragma unroll
  for (int u = 0; u < 4; u++) split2(hn[u], &g_HNh[e0 + u], &g_HNl[e0 + u]);
}

// ================= readout =================
__global__ void __launch_bounds__(128) k_readout(float* __restrict__ out) {
  __shared__ float sH[32 * 128];
  __shared__ float sal[32];
  const int g = blockIdx.x, t = threadIdx.x;
  const float4* h4 = (const float4*)(g_HNf + (size_t)g * 32 * 128);
  float4* s4 = (float4*)sH;
#pragma unroll
  for (int i = 0; i < 8; i++) s4[t + 128 * i] = h4[t + 128 * i];
  if (t < 32) sal[t] = g_alpha[g * 32 + t];
  __syncthreads();
  float acc = 0.f;
#pragma unroll
  for (int n = 0; n < 32; n++) acc += sH[n * 128 + t] * sal[n];
  out[(size_t)g * 256 + t] = acc;
  out[(size_t)g * 256 + 128 + t] = sH[31 * 128 + t];
}

// ================= host =================
extern "C" void kernel_launch(void* const* d_in, const int* in_sizes, int n_in,
                              void* d_out, int out_size) {
  const float* feat = (const float*)d_in[0];
  const float* cnt  = (const float*)d_in[1];
  const float* W_in = (const float*)d_in[2];
  const float* b_in = (const float*)d_in[3];
  const float* W_og = (const float*)d_in[4];
  const float* b_og = (const float*)d_in[5];
  const float* W_ih = (const float*)d_in[6];
  const float* b_ih = (const float*)d_in[7];
  const float* W_hh = (const float*)d_in[8];
  const float* b_hh = (const float*)d_in[9];
  const float* W_u  = (const float*)d_in[10];
  const float* W_v  = (const float*)d_in[11];
  const float* b_v  = (const float*)d_in[12];
  const float* w_e  = (const float*)d_in[13];
  const int*   src  = (const int*)d_in[14];
  const int*   dst  = (const int*)d_in[15];
  float* out = (float*)d_out;

  bf16 *featH, *featL, *AggH, *AggL, *HNh, *HNl;
  bf16 *WioH, *WioL, *WgH, *WgL, *WuH, *WuL, *WvH, *WvL;
  float *G, *FV, *biasY;
  cudaGetSymbolAddress((void**)&featH, g_featH);
  cudaGetSymbolAddress((void**)&featL, g_featL);
  cudaGetSymbolAddress((void**)&AggH, g_AggH);
  cudaGetSymbolAddress((void**)&AggL, g_AggL);
  cudaGetSymbolAddress((void**)&HNh, g_HNh);
  cudaGetSymbolAddress((void**)&HNl, g_HNl);
  cudaGetSymbolAddress((void**)&G, g_G);
  cudaGetSymbolAddress((void**)&FV, g_FV);
  cudaGetSymbolAddress((void**)&WioH, g_WioH);
  cudaGetSymbolAddress((void**)&WioL, g_WioL);
  cudaGetSymbolAddress((void**)&WgH, g_WgH);
  cudaGetSymbolAddress((void**)&WgL, g_WgL);
  cudaGetSymbolAddress((void**)&WuH, g_WuH);
  cudaGetSymbolAddress((void**)&WuL, g_WuL);
  cudaGetSymbolAddress((void**)&WvH, g_WvH);
  cudaGetSymbolAddress((void**)&WvL, g_WvL);
  cudaGetSymbolAddress((void**)&biasY, g_biasY);

  const int SMEM = 131072;
  static bool attr_done = false;
  if (!attr_done) {
    cudaFuncSetAttribute(k_mma<EPI_PLAIN>, cudaFuncAttributeMaxDynamicSharedMemorySize, SMEM);
    cudaFuncSetAttribute(k_mma<EPI_GATES>, cudaFuncAttributeMaxDynamicSharedMemorySize, SMEM);
    cudaFuncSetAttribute(k_mma<EPI_AGG>,   cudaFuncAttributeMaxDynamicSharedMemorySize, SMEM);
    cudaFuncSetAttribute(k_mma<EPI_ALPHA>, cudaFuncAttributeMaxDynamicSharedMemorySize, SMEM);
    attr_done = true;
  }

  const int MB = NNODE / 128;  // 2048

  k_zero_adj<<<512, 256>>>();
  k_build_adj<<<NEDGE / 256, 256>>>(src, dst);
  k_pack<<<256, 256>>>(W_in, W_og, W_ih, W_hh, W_u, W_v, b_in, b_og, b_ih, b_hh);
  k_split_feat<<<2048, 256>>>(feat);

  // Y = feat @ [W_in;W_og]^T + biasY  -> fused per-graph aggregation -> Agg hi/lo
  k_mma<EPI_AGG><<<dim3(MB, 2), 256, SMEM>>>(
      featH, featL, 128, featH, featL, 128, 128,
      WioH, WioL, 128, biasY, nullptr, 0, nullptr, nullptr);

  // gates: [Agg|feat] @ Wg^T -> G (bias added in k_gru)
  k_mma<EPI_GATES><<<dim3(MB, 4), 256, SMEM>>>(
      AggH, AggL, 256, featH, featL, 128, 256,
      WgH, WgL, 384, nullptr, G, 512, nullptr, nullptr);

  k_gru<<<NNODE * 32 / 256, 256>>>(feat);

  // FV = hn[last] @ W_v^T + b_v
  k_mma<EPI_PLAIN><<<dim3(NGRAPH / 128, 1), 256, SMEM>>>(
      HNh + 31 * 128, HNl + 31 * 128, 4096,
      HNh + 31 * 128, HNl + 31 * 128, 4096, 128,
      WvH, WvL, 128, b_v, FV, 128, nullptr, nullptr);

  // U = hn @ W_u^T -> fused attention -> alpha
  k_mma<EPI_ALPHA><<<dim3(MB, 1), 256, SMEM>>>(
      HNh, HNl, 128, HNh, HNl, 128, 128,
      WuH, WuL, 128, nullptr, nullptr, 0, cnt, w_e);

  k_readout<<<NGRAPH, 128>>>(out);
}